// round 14
// baseline (speedup 1.0000x reference)
#include <cuda_runtime.h>
#include <cstdint>

// ChannelDropout, two-phase with PDL overlap:
//   Phase A: scale[ch] = kept(ch) / (eps + proba(ch)), one warp per channel.
//            Triggers programmatic launch completion at entry so phase B's
//            blocks launch concurrently with A.
//   Phase B: pure HBM streamer (R6 structure, 76.4% DRAM measured). Issues its
//            8 batched LDG.128 FIRST, then cudaGridDependencySynchronize()
//            (waits for A's g_scale writes), then gathers scale & stores.
//
// Shapes: B=64, C=273, T=3000.  T/4 = 750 float4 per channel.

#define CD_TVEC   750                  // float4 per channel
#define CD_NMC    100
#define CD_DROP   0.2f
#define CD_EPS    1e-8f
#define CD_VPT    8                    // float4 per thread
#define CD_BLK    256
#define CD_TILE   (CD_BLK * CD_VPT)    // 2048 float4 per block

__device__ float g_scale[18432];       // >= B*C = 17472 (static scratch)

// ---------------- Phase A: per-channel scale, one warp per channel ----------
__global__ __launch_bounds__(256)
void cd_scale_kernel(const float2* __restrict__ pos,
                     const float*  __restrict__ center,
                     const float2* __restrict__ mc,
                     int BC)
{
#if __CUDA_ARCH__ >= 900
    cudaTriggerProgrammaticLaunchCompletion();   // let phase B start now
#endif
    const int warp = (blockIdx.x * blockDim.x + threadIdx.x) >> 5;
    const int lane = threadIdx.x & 31;
    if (warp >= BC) return;

    const float2 p  = pos[warp];
    const float  px = p.x, py = p.y;

    // kept: distance from ban center (no FMA contraction -> match jax fp32)
    const float dx = px - center[0];
    const float dy = py - center[1];
    const float d2 = __fadd_rn(__fmul_rn(dx, dx), __fmul_rn(dy, dy));
    const float kept = (sqrtf(d2) > CD_DROP) ? 1.0f : 0.0f;

    // Monte-Carlo: 32 lanes split the 100 trials (3-4 each)
    int cnt = 0;
#pragma unroll
    for (int t = lane; t < CD_NMC; t += 32) {
        const float2 m   = mc[t];
        const float  ddx = px - m.x;
        const float  ddy = py - m.y;
        const float  dd2 = __fadd_rn(__fmul_rn(ddx, ddx),
                                     __fmul_rn(ddy, ddy));
        cnt += (sqrtf(dd2) > CD_DROP) ? 1 : 0;
    }
#pragma unroll
    for (int off = 16; off > 0; off >>= 1)
        cnt += __shfl_xor_sync(0xffffffffu, cnt, off);

    if (lane == 0) {
        const float proba = (float)cnt / (float)CD_NMC;
        g_scale[warp] = kept / (CD_EPS + proba);
    }
}

// ---------------- Phase B: flat stream (R6 structure + grid-dep sync) -------
__global__ __launch_bounds__(CD_BLK)
void cd_stream_kernel(const float4* __restrict__ sig,
                      float4* __restrict__ out,
                      int total_vec)
{
    const int base = blockIdx.x * CD_TILE + threadIdx.x;

    if (base + (CD_VPT - 1) * CD_BLK < total_vec) {
        // Fast path: full tile -> 8 batched LDG.128 up front.
        float4 v[CD_VPT];
#pragma unroll
        for (int j = 0; j < CD_VPT; j++)
            v[j] = __ldcs(&sig[base + j * CD_BLK]);

#if __CUDA_ARCH__ >= 900
        cudaGridDependencySynchronize();   // g_scale ready (overlapped with loads)
#endif
        float s[CD_VPT];
#pragma unroll
        for (int j = 0; j < CD_VPT; j++)
            s[j] = g_scale[(unsigned)(base + j * CD_BLK) / CD_TVEC];
#pragma unroll
        for (int j = 0; j < CD_VPT; j++) {
            float4 r;
            r.x = v[j].x * s[j];
            r.y = v[j].y * s[j];
            r.z = v[j].z * s[j];
            r.w = v[j].w * s[j];
            __stcs(&out[base + j * CD_BLK], r);
        }
    } else {
        // Tail tile (one block): predicated.
#if __CUDA_ARCH__ >= 900
        cudaGridDependencySynchronize();
#endif
#pragma unroll
        for (int j = 0; j < CD_VPT; j++) {
            const int idx = base + j * CD_BLK;
            if (idx < total_vec) {
                float4 v = __ldcs(&sig[idx]);
                const float s = g_scale[(unsigned)idx / CD_TVEC];
                float4 r;
                r.x = v.x * s;
                r.y = v.y * s;
                r.z = v.z * s;
                r.w = v.w * s;
                __stcs(&out[idx], r);
            }
        }
    }
}

extern "C" void kernel_launch(void* const* d_in, const int* in_sizes, int n_in,
                              void* d_out, int out_size)
{
    const float4* sig    = (const float4*)d_in[0];   // brain_sig  (B,C,T) fp32
    const float2* pos    = (const float2*)d_in[1];   // positions  (B,C,2)
    const float*  center = (const float*) d_in[2];   // center     (2,)
    const float2* mc     = (const float2*)d_in[3];   // mc_centers (100,2)
    float4*       out    = (float4*)d_out;

    const int BC        = in_sizes[1] / 2;           // 17472
    const int total_vec = in_sizes[0] / 4;           // 13,104,000

    // Phase A: one warp per channel -> 17472 warps -> 69 blocks of 256? No:
    // 17472/8 warps-per-block = 2184 blocks of 256 threads.
    const int a_blocks = (BC * 32 + 255) / 256;      // 2184
    cd_scale_kernel<<<a_blocks, 256>>>(pos, center, mc, BC);

    // Phase B with programmatic dependent launch (overlaps A).
    const int nblocks = (total_vec + CD_TILE - 1) / CD_TILE;  // 6399

    cudaLaunchConfig_t cfg = {};
    cfg.gridDim  = dim3(nblocks, 1, 1);
    cfg.blockDim = dim3(CD_BLK, 1, 1);
    cfg.dynamicSmemBytes = 0;
    cfg.stream   = 0;

    cudaLaunchAttribute attrs[1];
    attrs[0].id = cudaLaunchAttributeProgrammaticStreamSerialization;
    attrs[0].val.programmaticStreamSerializationAllowed = 1;
    cfg.attrs    = attrs;
    cfg.numAttrs = 1;

    cudaLaunchKernelEx(&cfg, cd_stream_kernel, sig, out, total_vec);
}

// round 16
// speedup vs baseline: 1.0548x; 1.0548x over previous
#include <cuda_runtime.h>
#include <cstdint>

// ChannelDropout, single fused kernel (R11 skeleton + prologue shrink):
//   out[i] = sig[i] * scale[i / 750]
//   scale[ch] = kept(ch) / (eps + mean_j(||pos[ch]-mc[j]|| > 0.2))
//
// Per 2048-float4 tile: batch-issue all 8 LDG.128/thread FIRST, then warps 0-3
// compute the <=4 channel scales this tile touches (hidden under the DRAM
// latency of the in-flight loads) using float2 loads + REDUX.SUM, sync,
// gather from smem, multiply, store.
//
// Shapes: B=64, C=273, T=3000.  T/4 = 750 float4 per channel.

#define CD_TVEC   750                  // float4 per channel
#define CD_NMC    100
#define CD_DROP   0.2f
#define CD_EPS    1e-8f
#define CD_VPT    8                    // float4 per thread
#define CD_BLK    256
#define CD_TILE   (CD_BLK * CD_VPT)    // 2048 float4 per block (spans <=4 ch)

__global__ __launch_bounds__(CD_BLK)
void cd_fused_kernel(const float4* __restrict__ sig,
                     const float2* __restrict__ pos,
                     const float*  __restrict__ center,
                     const float2* __restrict__ mc,
                     float4* __restrict__ out,
                     int total_vec, int BC)
{
    __shared__ float s_scale[4];

    const int tile0 = blockIdx.x * CD_TILE;
    const int base  = tile0 + threadIdx.x;
    const bool full = (tile0 + CD_TILE <= total_vec);

    // ---- 1) batch-issue the 8 sig loads (front-loaded MLP) ----
    float4 v[CD_VPT];
    if (full) {
#pragma unroll
        for (int j = 0; j < CD_VPT; j++)
            v[j] = __ldcs(&sig[base + j * CD_BLK]);
    } else {
#pragma unroll
        for (int j = 0; j < CD_VPT; j++)
            if (base + j * CD_BLK < total_vec)
                v[j] = __ldcs(&sig[base + j * CD_BLK]);
    }

    // ---- 2) warps 0-3: compute this tile's <=4 channel scales (hidden) ----
    const int wid      = threadIdx.x >> 5;
    const int lane     = threadIdx.x & 31;
    const int first_ch = tile0 / CD_TVEC;

    if (wid < 4) {
        const int ch = first_ch + wid;
        if (ch < BC) {
            const float2 p  = pos[ch];
            const float  px = p.x, py = p.y;

            // kept: distance from ban center (no FMA contraction -> match jax)
            const float dx = px - center[0];
            const float dy = py - center[1];
            const float d2 = __fadd_rn(__fmul_rn(dx, dx), __fmul_rn(dy, dy));
            const float kept = (sqrtf(d2) > CD_DROP) ? 1.0f : 0.0f;

            // Monte-Carlo: lanes parallel over the 100 trials (<=4 each),
            // fully unrolled so all mc loads batch-issue.
            int cnt = 0;
#pragma unroll
            for (int jj = 0; jj < 4; jj++) {
                const int t = lane + jj * 32;
                if (t < CD_NMC) {
                    const float2 m   = mc[t];
                    const float  ddx = px - m.x;
                    const float  ddy = py - m.y;
                    const float  dd2 = __fadd_rn(__fmul_rn(ddx, ddx),
                                                 __fmul_rn(ddy, ddy));
                    cnt += (sqrtf(dd2) > CD_DROP) ? 1 : 0;
                }
            }
            cnt = __reduce_add_sync(0xffffffffu, cnt);   // REDUX.SUM

            if (lane == 0) {
                const float proba = (float)cnt / (float)CD_NMC;
                s_scale[wid] = kept / (CD_EPS + proba);
            }
        }
    }
    __syncthreads();

    // ---- 3) gather scale from smem broadcast, multiply, store ----
    if (full) {
        float s[CD_VPT];
#pragma unroll
        for (int j = 0; j < CD_VPT; j++)
            s[j] = s_scale[(unsigned)(base + j * CD_BLK) / CD_TVEC - first_ch];
#pragma unroll
        for (int j = 0; j < CD_VPT; j++) {
            float4 r;
            r.x = v[j].x * s[j];
            r.y = v[j].y * s[j];
            r.z = v[j].z * s[j];
            r.w = v[j].w * s[j];
            __stcs(&out[base + j * CD_BLK], r);
        }
    } else {
#pragma unroll
        for (int j = 0; j < CD_VPT; j++) {
            const int idx = base + j * CD_BLK;
            if (idx < total_vec) {
                const float s = s_scale[(unsigned)idx / CD_TVEC - first_ch];
                float4 r;
                r.x = v[j].x * s;
                r.y = v[j].y * s;
                r.z = v[j].z * s;
                r.w = v[j].w * s;
                __stcs(&out[idx], r);
            }
        }
    }
}

extern "C" void kernel_launch(void* const* d_in, const int* in_sizes, int n_in,
                              void* d_out, int out_size)
{
    const float4* sig    = (const float4*)d_in[0];   // brain_sig  (B,C,T) fp32
    const float2* pos    = (const float2*)d_in[1];   // positions  (B,C,2)
    const float*  center = (const float*) d_in[2];   // center     (2,)
    const float2* mc     = (const float2*)d_in[3];   // mc_centers (100,2)
    float4*       out    = (float4*)d_out;

    const int BC        = in_sizes[1] / 2;           // 17472
    const int total_vec = in_sizes[0] / 4;           // 13,104,000

    const int nblocks = (total_vec + CD_TILE - 1) / CD_TILE;  // 6399
    cd_fused_kernel<<<nblocks, CD_BLK>>>(sig, pos, center, mc, out,
                                         total_vec, BC);
}